// round 4
// baseline (speedup 1.0000x reference)
#include <cuda_runtime.h>

// Max-unpool 2x2 stride 2, NHWC — persistent grid-stride version.
// x:      [16, 128, 128, 256] f32   (read once)
// pooled: [16,  64,  64, 256] f32   (read once)
// out:    [16, 128, 128, 256] f32   (write once)
// 604 MB mandatory streaming traffic; goal is max sustained HBM bandwidth.
// 1184 persistent blocks (148 SMs x 8 blocks) -> zero wave transitions,
// loads of the next iteration overlap stores of the current one.

static constexpr int N_  = 16;
static constexpr int H_  = 128;
static constexpr int W_  = 128;
static constexpr int C_  = 256;
static constexpr int HP_ = H_ / 2;
static constexpr int WP_ = W_ / 2;
static constexpr int C4_ = C_ / 4;            // 64 float4 per channel row
static constexpr int ROW4_ = W_ * C4_;        // x row stride in float4 (8192)
static constexpr int TOTAL4 = N_ * HP_ * WP_ * C4_;  // 4,194,304 work items

static constexpr int BLOCKS_  = 148 * 8;      // one full resident wave
static constexpr int THREADS_ = 256;

__global__ __launch_bounds__(THREADS_)
void unpool_kernel(const float4* __restrict__ x,
                   const float4* __restrict__ pooled,
                   float4* __restrict__ out)
{
    const int stride = BLOCKS_ * THREADS_;
    for (int i = blockIdx.x * THREADS_ + threadIdx.x; i < TOTAL4; i += stride) {
        // i -> ((n*HP + hp)*WP + wp)*C4 + c4
        int c4 = i & (C4_ - 1);
        int t  = i >> 6;            // / C4_
        int wp = t & (WP_ - 1);
        t >>= 6;                    // / WP_
        int hp = t & (HP_ - 1);
        int n  = t >> 6;            // / HP_

        int base = ((n * H_ + 2 * hp) * W_ + 2 * wp) * C4_ + c4;

        float4 v00 = __ldcs(x + base);
        float4 v01 = __ldcs(x + base + C4_);
        float4 v10 = __ldcs(x + base + ROW4_);
        float4 v11 = __ldcs(x + base + ROW4_ + C4_);
        float4 pv  = __ldcs(pooled + i);

        float a0[4] = {v00.x, v00.y, v00.z, v00.w};
        float a1[4] = {v01.x, v01.y, v01.z, v01.w};
        float a2[4] = {v10.x, v10.y, v10.z, v10.w};
        float a3[4] = {v11.x, v11.y, v11.z, v11.w};
        float p4[4] = {pv.x, pv.y, pv.z, pv.w};

        float o0[4], o1[4], o2[4], o3[4];

        #pragma unroll
        for (int l = 0; l < 4; ++l) {
            float best = a0[l];
            int bi = 0;
            if (a1[l] > best) { best = a1[l]; bi = 1; }
            if (a2[l] > best) { best = a2[l]; bi = 2; }
            if (a3[l] > best) {              bi = 3; }
            float val = fmaxf(p4[l], 0.0f);
            o0[l] = (bi == 0) ? val : 0.0f;
            o1[l] = (bi == 1) ? val : 0.0f;
            o2[l] = (bi == 2) ? val : 0.0f;
            o3[l] = (bi == 3) ? val : 0.0f;
        }

        __stcs(out + base,               make_float4(o0[0], o0[1], o0[2], o0[3]));
        __stcs(out + base + C4_,         make_float4(o1[0], o1[1], o1[2], o1[3]));
        __stcs(out + base + ROW4_,       make_float4(o2[0], o2[1], o2[2], o2[3]));
        __stcs(out + base + ROW4_ + C4_, make_float4(o3[0], o3[1], o3[2], o3[3]));
    }
}

extern "C" void kernel_launch(void* const* d_in, const int* in_sizes, int n_in,
                              void* d_out, int out_size)
{
    const float4* x      = (const float4*)d_in[0];
    const float4* pooled = (const float4*)d_in[1];
    float4* out          = (float4*)d_out;

    unpool_kernel<<<BLOCKS_, THREADS_>>>(x, pooled, out);
}

// round 5
// speedup vs baseline: 1.0805x; 1.0805x over previous
#include <cuda_runtime.h>

// Max-unpool 2x2 stride 2, NHWC. R3 per-thread body (28 regs, .cs streaming
// hints), block size 512 for longer contiguous address streams per block.
// x:      [16, 128, 128, 256] f32   (read once)
// pooled: [16,  64,  64, 256] f32   (read once)
// out:    [16, 128, 128, 256] f32   (write once)

static constexpr int N_  = 16;
static constexpr int H_  = 128;
static constexpr int W_  = 128;
static constexpr int C_  = 256;
static constexpr int HP_ = H_ / 2;
static constexpr int WP_ = W_ / 2;
static constexpr int C4_ = C_ / 4;            // 64 float4 per channel row
static constexpr int ROW4_ = W_ * C4_;        // x row stride in float4 (8192)
static constexpr int TOTAL4 = N_ * HP_ * WP_ * C4_;  // 4,194,304

static constexpr int THREADS_ = 512;

__global__ __launch_bounds__(THREADS_)
void unpool_kernel(const float4* __restrict__ x,
                   const float4* __restrict__ pooled,
                   float4* __restrict__ out)
{
    int i = blockIdx.x * THREADS_ + threadIdx.x;
    if (i >= TOTAL4) return;

    // i -> ((n*HP + hp)*WP + wp)*C4 + c4
    int c4 = i & (C4_ - 1);
    int t  = i >> 6;            // / C4_
    int wp = t & (WP_ - 1);
    t >>= 6;                    // / WP_
    int hp = t & (HP_ - 1);
    int n  = t >> 6;            // / HP_

    int base = ((n * H_ + 2 * hp) * W_ + 2 * wp) * C4_ + c4;

    float4 v00 = __ldcs(x + base);
    float4 v01 = __ldcs(x + base + C4_);
    float4 v10 = __ldcs(x + base + ROW4_);
    float4 v11 = __ldcs(x + base + ROW4_ + C4_);
    float4 pv  = __ldcs(pooled + i);

    float a0[4] = {v00.x, v00.y, v00.z, v00.w};
    float a1[4] = {v01.x, v01.y, v01.z, v01.w};
    float a2[4] = {v10.x, v10.y, v10.z, v10.w};
    float a3[4] = {v11.x, v11.y, v11.z, v11.w};
    float p4[4] = {pv.x, pv.y, pv.z, pv.w};

    float o0[4], o1[4], o2[4], o3[4];

    #pragma unroll
    for (int l = 0; l < 4; ++l) {
        float best = a0[l];
        int bi = 0;
        if (a1[l] > best) { best = a1[l]; bi = 1; }
        if (a2[l] > best) { best = a2[l]; bi = 2; }
        if (a3[l] > best) {              bi = 3; }
        float val = fmaxf(p4[l], 0.0f);
        o0[l] = (bi == 0) ? val : 0.0f;
        o1[l] = (bi == 1) ? val : 0.0f;
        o2[l] = (bi == 2) ? val : 0.0f;
        o3[l] = (bi == 3) ? val : 0.0f;
    }

    __stcs(out + base,               make_float4(o0[0], o0[1], o0[2], o0[3]));
    __stcs(out + base + C4_,         make_float4(o1[0], o1[1], o1[2], o1[3]));
    __stcs(out + base + ROW4_,       make_float4(o2[0], o2[1], o2[2], o2[3]));
    __stcs(out + base + ROW4_ + C4_, make_float4(o3[0], o3[1], o3[2], o3[3]));
}

extern "C" void kernel_launch(void* const* d_in, const int* in_sizes, int n_in,
                              void* d_out, int out_size)
{
    const float4* x      = (const float4*)d_in[0];
    const float4* pooled = (const float4*)d_in[1];
    float4* out          = (float4*)d_out;

    const int blocks = (TOTAL4 + THREADS_ - 1) / THREADS_;
    unpool_kernel<<<blocks, THREADS_>>>(x, pooled, out);
}

// round 6
// speedup vs baseline: 1.0904x; 1.0092x over previous
#include <cuda_runtime.h>

// Max-unpool 2x2 stride 2, NHWC — final form.
// x:      [16, 128, 128, 256] f32   (read once)
// pooled: [16,  64,  64, 256] f32   (read once)
// out:    [16, 128, 128, 256] f32   (write once)
//
// HBM-bound: ~552 MB actual DRAM traffic at ~6.6 TB/s sustained.
// Best config found: 1 float4 per thread (28 regs, occ ~80%), 256-thread
// blocks, .cs evict-first hints. This version trims the bounds guard
// (exact grid) and uses a closed-form index map:
//   i    = ((n*64+hp)*64 + wp)*64 + c4          (pooled float4 index)
//   base = ((n*128+2hp)*128 + 2wp)*64 + c4      (x/out float4 index)
//        = 4*i - 2*(i & 4095) - (i & 63)

static constexpr int C4_   = 64;            // float4 per channel row
static constexpr int ROW4_ = 128 * C4_;     // x row stride in float4 (8192)
static constexpr int TOTAL4 = 16 * 64 * 64 * C4_;  // 4,194,304 = 16384*256

static constexpr int THREADS_ = 256;
static constexpr int BLOCKS_  = TOTAL4 / THREADS_;  // exact, no tail

__global__ __launch_bounds__(THREADS_)
void unpool_kernel(const float4* __restrict__ x,
                   const float4* __restrict__ pooled,
                   float4* __restrict__ out)
{
    int i = blockIdx.x * THREADS_ + threadIdx.x;

    // base index into x/out at the top-left of this window's 2x2 block
    int base = (i << 2) - ((i & 4095) << 1) - (i & 63);

    float4 v00 = __ldcs(x + base);
    float4 v01 = __ldcs(x + base + C4_);
    float4 v10 = __ldcs(x + base + ROW4_);
    float4 v11 = __ldcs(x + base + ROW4_ + C4_);
    float4 pv  = __ldcs(pooled + i);

    float a0[4] = {v00.x, v00.y, v00.z, v00.w};
    float a1[4] = {v01.x, v01.y, v01.z, v01.w};
    float a2[4] = {v10.x, v10.y, v10.z, v10.w};
    float a3[4] = {v11.x, v11.y, v11.z, v11.w};
    float p4[4] = {pv.x, pv.y, pv.z, pv.w};

    float o0[4], o1[4], o2[4], o3[4];

    #pragma unroll
    for (int l = 0; l < 4; ++l) {
        float best = a0[l];
        int bi = 0;
        if (a1[l] > best) { best = a1[l]; bi = 1; }
        if (a2[l] > best) { best = a2[l]; bi = 2; }
        if (a3[l] > best) {              bi = 3; }
        float val = fmaxf(p4[l], 0.0f);
        o0[l] = (bi == 0) ? val : 0.0f;
        o1[l] = (bi == 1) ? val : 0.0f;
        o2[l] = (bi == 2) ? val : 0.0f;
        o3[l] = (bi == 3) ? val : 0.0f;
    }

    __stcs(out + base,               make_float4(o0[0], o0[1], o0[2], o0[3]));
    __stcs(out + base + C4_,         make_float4(o1[0], o1[1], o1[2], o1[3]));
    __stcs(out + base + ROW4_,       make_float4(o2[0], o2[1], o2[2], o2[3]));
    __stcs(out + base + ROW4_ + C4_, make_float4(o3[0], o3[1], o3[2], o3[3]));
}

extern "C" void kernel_launch(void* const* d_in, const int* in_sizes, int n_in,
                              void* d_out, int out_size)
{
    const float4* x      = (const float4*)d_in[0];
    const float4* pooled = (const float4*)d_in[1];
    float4* out          = (float4*)d_out;

    unpool_kernel<<<BLOCKS_, THREADS_>>>(x, pooled, out);
}